// round 4
// baseline (speedup 1.0000x reference)
#include <cuda_runtime.h>

#define B_   256
#define N_   64
#define K_   12
#define D_   128
#define ROWS 16384

// ---------------- device scratch (allocation-free) ----------------
__device__ float g_uq[D_];
__device__ float g_uk[D_];
__device__ float g_c;
__device__ float g_As[(size_t)ROWS * D_];   // 8 MB combined vectors
__device__ float g_Ssum[ROWS];              // attention sums

__device__ __forceinline__ float dot4(float4 a, float4 b) {
    return fmaf(a.x, b.x, fmaf(a.y, b.y, fmaf(a.z, b.z, a.w * b.w)));
}
__device__ __forceinline__ void ffma2(unsigned long long& d, unsigned long long a, unsigned long long b) {
    asm("fma.rn.f32x2 %0, %1, %2, %0;" : "+l"(d) : "l"(a), "l"(b));
}
__device__ __forceinline__ unsigned long long pack2(float x) {
    unsigned long long r;
    asm("mov.b64 %0, {%1, %1};" : "=l"(r) : "f"(x));
    return r;
}
__device__ __forceinline__ float2 unpack2(unsigned long long v) {
    float2 f;
    asm("mov.b64 {%0, %1}, %2;" : "=f"(f.x), "=f"(f.y) : "l"(v));
    return f;
}

// ---------------- prologue: uq = Wq@waq, uk = Wk@wak, c (32 blocks) --------
__global__ __launch_bounds__(128)
void gat_prologue(const float* __restrict__ Wq, const float* __restrict__ bq,
                  const float* __restrict__ Wk, const float* __restrict__ bk,
                  const float* __restrict__ waq, const float* __restrict__ wak,
                  const float* __restrict__ ba) {
    const int wid = threadIdx.x >> 5;
    const int l   = threadIdx.x & 31;
    const int r   = blockIdx.x * 4 + wid;   // row 0..127

    // warp computes uq[r], uk[r]
    float4 a = __ldg((const float4*)(Wq + r * D_) + l);
    float4 b = __ldg((const float4*)waq + l);
    float4 c2 = __ldg((const float4*)(Wk + r * D_) + l);
    float4 d2 = __ldg((const float4*)wak + l);
    float sq = dot4(a, b);
    float sk = dot4(c2, d2);
#pragma unroll
    for (int off = 16; off; off >>= 1) {
        sq += __shfl_xor_sync(0xFFFFFFFFu, sq, off);
        sk += __shfl_xor_sync(0xFFFFFFFFu, sk, off);
    }
    if (l == 0) { g_uq[r] = sq; g_uk[r] = sk; }

    // block 0 also computes c
    if (blockIdx.x == 0) {
        const int i = threadIdx.x;
        float p = __ldg(bq + i) * __ldg(waq + i) + __ldg(bk + i) * __ldg(wak + i);
#pragma unroll
        for (int off = 16; off; off >>= 1) p += __shfl_xor_sync(0xFFFFFFFFu, p, off);
        __shared__ float red[4];
        if (l == 0) red[wid] = p;
        __syncthreads();
        if (i == 0) g_c = red[0] + red[1] + red[2] + red[3] + __ldg(ba);
    }
}

// ---------------- kernel A: attention + weighted combine (streaming) -------
#define A_WARPS 8
__global__ __launch_bounds__(A_WARPS * 32, 2)
void gat_attn(const float* __restrict__ nodes, const float* __restrict__ nbrs,
              const float* __restrict__ mask)
{
    const int wid = threadIdx.x >> 5;
    const int l   = threadIdx.x & 31;
    const int row = blockIdx.x * A_WARPS + wid;

    const float4 uq4 = ((const float4*)g_uq)[l];
    const float4 uk4 = ((const float4*)g_uk)[l];
    const float  cc  = g_c;

    // ---- prefetch mask in lanes 1..12 (overlaps the row loads below) ----
    float mj = 1.0f;
    if (l >= 1 && l <= K_) mj = __ldg(mask + (size_t)row * K_ + (l - 1));

    // ---- load node + 12 neighbors (lane l owns elements 4l..4l+3) ----
    float4 nh0 = __ldg((const float4*)(nodes + (size_t)row * D_) + l);
    const float4* np = (const float4*)(nbrs + (size_t)row * (K_ * D_));
    float4 nhj[K_];
    float  kd[K_ + 1];
    float  qd = dot4(nh0, uq4);
    kd[0] = dot4(nh0, uk4);
#pragma unroll
    for (int j = 0; j < K_; ++j) {
        float4 v = __ldg(np + j * 32 + l);
        nhj[j] = v;
        kd[j + 1] = dot4(v, uk4);
    }

    // ---- butterfly reduce 14 dots across the warp ----
#pragma unroll
    for (int off = 16; off; off >>= 1) {
        qd += __shfl_xor_sync(0xFFFFFFFFu, qd, off);
#pragma unroll
        for (int j = 0; j <= K_; ++j)
            kd[j] += __shfl_xor_sync(0xFFFFFFFFu, kd[j], off);
    }

    // ---- masked LeakyReLU-exp softmax (mask via shfl broadcast) ----
    const float sbase = qd + cc;
    float e[K_ + 1];
    float s = 0.f;
#pragma unroll
    for (int j = 0; j <= K_; ++j) {
        float t = kd[j] + sbase;
        t = (t >= 0.f) ? t : 0.2f * t;
        float ej = __expf(t) * __shfl_sync(0xFFFFFFFFu, mj, j);
        e[j] = ej;
        s += ej;
    }
    const float inv = 1.f / (s + 1e-16f);

    // ---- weighted combine ----
    float a0 = e[0] * inv;
    float4 w = make_float4(a0 * nh0.x, a0 * nh0.y, a0 * nh0.z, a0 * nh0.w);
#pragma unroll
    for (int j = 0; j < K_; ++j) {
        float a = e[j + 1] * inv;
        w.x = fmaf(a, nhj[j].x, w.x);
        w.y = fmaf(a, nhj[j].y, w.y);
        w.z = fmaf(a, nhj[j].z, w.z);
        w.w = fmaf(a, nhj[j].w, w.w);
    }

    ((float4*)(g_As + (size_t)row * D_))[l] = w;
    if (l == 0) g_Ssum[row] = s * inv;
}

// ---------------- kernel B: [16384,128] x Wv[128,128] + asum*bv ------------
#define TILE_M 64
#define B_THREADS 128
#define B_SM_FLOATS (16384 + TILE_M * 128 + 64)

__global__ __launch_bounds__(B_THREADS, 2)
void gat_gemm(const float* __restrict__ Wv, const float* __restrict__ bv,
              float* __restrict__ out)
{
    extern __shared__ float sm[];
    float* wv_s   = sm;                  // [128][128]
    float* as_s   = sm + 16384;          // [64][128]
    float* ssum_s = as_s + TILE_M * 128; // [64]

    const int tid  = threadIdx.x;
    const int row0 = blockIdx.x * TILE_M;

    // cooperative loads
    {
        const float4* src = (const float4*)Wv;
        float4* dst = (float4*)wv_s;
#pragma unroll
        for (int i = tid; i < 16384 / 4; i += B_THREADS) dst[i] = src[i];
        const float4* asrc = (const float4*)(g_As + (size_t)row0 * D_);
        float4* adst = (float4*)as_s;
#pragma unroll
        for (int i = tid; i < TILE_M * 128 / 4; i += B_THREADS) adst[i] = asrc[i];
        if (tid < TILE_M) ssum_s[tid] = g_Ssum[row0 + tid];
    }
    __syncthreads();

    // thread tile: 8 rows x 8 cols
    const int m_id = tid >> 4;   // 0..7
    const int n_id = tid & 15;   // 0..15
    const float* a_base = as_s + m_id * 8 * 128;
    const float* b_base = wv_s + n_id * 8;

    unsigned long long acc[8][4];
#pragma unroll
    for (int r = 0; r < 8; ++r)
#pragma unroll
        for (int c = 0; c < 4; ++c) acc[r][c] = 0ull;

#pragma unroll 2
    for (int k = 0; k < 128; k += 4) {
        float4 a4[8];
#pragma unroll
        for (int r = 0; r < 8; ++r)
            a4[r] = *(const float4*)(a_base + r * 128 + k);
#pragma unroll
        for (int kk = 0; kk < 4; ++kk) {
            const float* bp = b_base + (k + kk) * 128;
            ulonglong2 b01 = *(const ulonglong2*)bp;
            ulonglong2 b23 = *(const ulonglong2*)(bp + 4);
#pragma unroll
            for (int r = 0; r < 8; ++r) {
                float av = (kk == 0) ? a4[r].x : (kk == 1) ? a4[r].y
                         : (kk == 2) ? a4[r].z : a4[r].w;
                unsigned long long ap = pack2(av);
                ffma2(acc[r][0], ap, b01.x);
                ffma2(acc[r][1], ap, b01.y);
                ffma2(acc[r][2], ap, b23.x);
                ffma2(acc[r][3], ap, b23.y);
            }
        }
    }

    // epilogue: + asum * bv
    const float* bvp = bv + n_id * 8;
    float4 bva = __ldg((const float4*)bvp);
    float4 bvb = __ldg((const float4*)bvp + 1);
#pragma unroll
    for (int r = 0; r < 8; ++r) {
        float srow = ssum_s[m_id * 8 + r];
        float2 p0 = unpack2(acc[r][0]);
        float2 p1 = unpack2(acc[r][1]);
        float2 p2 = unpack2(acc[r][2]);
        float2 p3 = unpack2(acc[r][3]);
        float4 o0 = make_float4(fmaf(srow, bva.x, p0.x), fmaf(srow, bva.y, p0.y),
                                fmaf(srow, bva.z, p1.x), fmaf(srow, bva.w, p1.y));
        float4 o1 = make_float4(fmaf(srow, bvb.x, p2.x), fmaf(srow, bvb.y, p2.y),
                                fmaf(srow, bvb.z, p3.x), fmaf(srow, bvb.w, p3.y));
        float* op = out + (size_t)(row0 + m_id * 8 + r) * D_ + n_id * 8;
        *(float4*)op       = o0;
        *(float4*)(op + 4) = o1;
    }
}

extern "C" void kernel_launch(void* const* d_in, const int* in_sizes, int n_in,
                              void* d_out, int out_size) {
    const float* nodes = (const float*)d_in[0];
    const float* nbrs  = (const float*)d_in[1];
    const float* mask  = (const float*)d_in[2];
    const float* Wq    = (const float*)d_in[3];
    const float* bq    = (const float*)d_in[4];
    const float* Wk    = (const float*)d_in[5];
    const float* bk    = (const float*)d_in[6];
    const float* Wv    = (const float*)d_in[7];
    const float* bv    = (const float*)d_in[8];
    const float* waq   = (const float*)d_in[9];
    const float* wak   = (const float*)d_in[10];
    const float* ba    = (const float*)d_in[11];
    float* out = (float*)d_out;

    cudaFuncSetAttribute(gat_gemm, cudaFuncAttributeMaxDynamicSharedMemorySize,
                         B_SM_FLOATS * 4);

    gat_prologue<<<32, 128>>>(Wq, bq, Wk, bk, waq, wak, ba);
    gat_attn<<<ROWS / A_WARPS, A_WARPS * 32>>>(nodes, nbrs, mask);
    gat_gemm<<<ROWS / TILE_M, B_THREADS, B_SM_FLOATS * 4>>>(Wv, bv, out);
}

// round 5
// speedup vs baseline: 1.3856x; 1.3856x over previous
#include <cuda_runtime.h>

#define B_   256
#define N_   64
#define K_   12
#define D_   128
#define ROWS 16384

// ---------------- device scratch (allocation-free) ----------------
__device__ float g_uq[D_];
__device__ float g_uk[D_];
__device__ float g_c;
__device__ float g_As[(size_t)ROWS * D_];   // 8 MB combined vectors
__device__ float g_Ssum[ROWS];              // attention sums

__device__ __forceinline__ float dot4(float4 a, float4 b) {
    return fmaf(a.x, b.x, fmaf(a.y, b.y, fmaf(a.z, b.z, a.w * b.w)));
}
__device__ __forceinline__ void ffma2(unsigned long long& d, unsigned long long a, unsigned long long b) {
    asm("fma.rn.f32x2 %0, %1, %2, %0;" : "+l"(d) : "l"(a), "l"(b));
}
__device__ __forceinline__ unsigned long long pack2(float x) {
    unsigned long long r;
    asm("mov.b64 %0, {%1, %1};" : "=l"(r) : "f"(x));
    return r;
}
__device__ __forceinline__ float2 unpack2(unsigned long long v) {
    float2 f;
    asm("mov.b64 {%0, %1}, %2;" : "=f"(f.x), "=f"(f.y) : "l"(v));
    return f;
}

// ---------------- prologue: uq = Wq@waq, uk = Wk@wak, c (32 blocks) --------
__global__ __launch_bounds__(128)
void gat_prologue(const float* __restrict__ Wq, const float* __restrict__ bq,
                  const float* __restrict__ Wk, const float* __restrict__ bk,
                  const float* __restrict__ waq, const float* __restrict__ wak,
                  const float* __restrict__ ba) {
    const int wid = threadIdx.x >> 5;
    const int l   = threadIdx.x & 31;
    const int r   = blockIdx.x * 4 + wid;   // row 0..127

    float4 a  = __ldg((const float4*)(Wq + r * D_) + l);
    float4 b  = __ldg((const float4*)waq + l);
    float4 c2 = __ldg((const float4*)(Wk + r * D_) + l);
    float4 d2 = __ldg((const float4*)wak + l);
    float sq = dot4(a, b);
    float sk = dot4(c2, d2);
#pragma unroll
    for (int off = 16; off; off >>= 1) {
        sq += __shfl_xor_sync(0xFFFFFFFFu, sq, off);
        sk += __shfl_xor_sync(0xFFFFFFFFu, sk, off);
    }
    if (l == 0) { g_uq[r] = sq; g_uk[r] = sk; }

    if (blockIdx.x == 0) {
        const int i = threadIdx.x;
        float p = __ldg(bq + i) * __ldg(waq + i) + __ldg(bk + i) * __ldg(wak + i);
#pragma unroll
        for (int off = 16; off; off >>= 1) p += __shfl_xor_sync(0xFFFFFFFFu, p, off);
        __shared__ float red[4];
        if (l == 0) red[wid] = p;
        __syncthreads();
        if (i == 0) g_c = red[0] + red[1] + red[2] + red[3] + __ldg(ba);
    }
}

// ---------------- kernel A: attention + weighted combine (two-pass) --------
#define A_WARPS 8
__global__ __launch_bounds__(A_WARPS * 32, 3)
void gat_attn(const float* __restrict__ nodes, const float* __restrict__ nbrs,
              const float* __restrict__ mask)
{
    const int wid = threadIdx.x >> 5;
    const int l   = threadIdx.x & 31;
    const int row = blockIdx.x * A_WARPS + wid;

    const float4 uq4 = ((const float4*)g_uq)[l];
    const float4 uk4 = ((const float4*)g_uk)[l];
    const float  cc  = g_c;

    // ---- prefetch mask: 12 uniform loads, issued before the row stream ----
    float m[K_];
    const float* mp = mask + (size_t)row * K_;
#pragma unroll
    for (int j = 0; j < K_; ++j) m[j] = __ldg(mp + j);

    // ---- pass 1: load node + neighbors, compute 14 dot partials ----
    float4 nh0 = __ldg((const float4*)(nodes + (size_t)row * D_) + l);
    const float4* np = (const float4*)(nbrs + (size_t)row * (K_ * D_));
    float kd[K_ + 1];
    float qd = dot4(nh0, uq4);
    kd[0] = dot4(nh0, uk4);
#pragma unroll
    for (int j = 0; j < K_; ++j) {
        float4 v = __ldg(np + j * 32 + l);
        kd[j + 1] = dot4(v, uk4);
    }

    // ---- butterfly reduce 14 dots across the warp ----
#pragma unroll
    for (int off = 16; off; off >>= 1) {
        qd += __shfl_xor_sync(0xFFFFFFFFu, qd, off);
#pragma unroll
        for (int j = 0; j <= K_; ++j)
            kd[j] += __shfl_xor_sync(0xFFFFFFFFu, kd[j], off);
    }

    // ---- masked LeakyReLU-exp softmax (mask already in registers) ----
    const float sbase = qd + cc;
    float s = 0.f;
#pragma unroll
    for (int j = 0; j <= K_; ++j) {
        float t = kd[j] + sbase;
        t = (t >= 0.f) ? t : 0.2f * t;
        float ej = __expf(t);
        if (j) ej *= m[j - 1];
        kd[j] = ej;              // reuse kd as e
        s += ej;
    }
    const float inv = 1.f / (s + 1e-16f);
#pragma unroll
    for (int j = 0; j <= K_; ++j) kd[j] *= inv;   // normalized attention

    // ---- pass 2: reload neighbors (L1/L2 hits) and combine ----
    float4 w = make_float4(kd[0] * nh0.x, kd[0] * nh0.y,
                           kd[0] * nh0.z, kd[0] * nh0.w);
#pragma unroll
    for (int j = 0; j < K_; ++j) {
        float4 v = __ldg(np + j * 32 + l);
        float a = kd[j + 1];
        w.x = fmaf(a, v.x, w.x);
        w.y = fmaf(a, v.y, w.y);
        w.z = fmaf(a, v.z, w.z);
        w.w = fmaf(a, v.w, w.w);
    }

    ((float4*)(g_As + (size_t)row * D_))[l] = w;
    if (l == 0) g_Ssum[row] = s * inv;
}

// ---------------- kernel B: [16384,128] x Wv[128,128] + asum*bv ------------
#define TILE_M 64
#define B_THREADS 128
#define B_SM_FLOATS (16384 + TILE_M * 128 + 64)

__global__ __launch_bounds__(B_THREADS, 2)
void gat_gemm(const float* __restrict__ Wv, const float* __restrict__ bv,
              float* __restrict__ out)
{
    extern __shared__ float sm[];
    float* wv_s   = sm;                  // [128][128]
    float* as_s   = sm + 16384;          // [64][128]
    float* ssum_s = as_s + TILE_M * 128; // [64]

    const int tid  = threadIdx.x;
    const int row0 = blockIdx.x * TILE_M;

    {
        const float4* src = (const float4*)Wv;
        float4* dst = (float4*)wv_s;
#pragma unroll
        for (int i = tid; i < 16384 / 4; i += B_THREADS) dst[i] = src[i];
        const float4* asrc = (const float4*)(g_As + (size_t)row0 * D_);
        float4* adst = (float4*)as_s;
#pragma unroll
        for (int i = tid; i < TILE_M * 128 / 4; i += B_THREADS) adst[i] = asrc[i];
        if (tid < TILE_M) ssum_s[tid] = g_Ssum[row0 + tid];
    }
    __syncthreads();

    const int m_id = tid >> 4;   // 0..7
    const int n_id = tid & 15;   // 0..15
    const float* a_base = as_s + m_id * 8 * 128;
    const float* b_base = wv_s + n_id * 8;

    unsigned long long acc[8][4];
#pragma unroll
    for (int r = 0; r < 8; ++r)
#pragma unroll
        for (int c = 0; c < 4; ++c) acc[r][c] = 0ull;

#pragma unroll 2
    for (int k = 0; k < 128; k += 4) {
        float4 a4[8];
#pragma unroll
        for (int r = 0; r < 8; ++r)
            a4[r] = *(const float4*)(a_base + r * 128 + k);
#pragma unroll
        for (int kk = 0; kk < 4; ++kk) {
            const float* bp = b_base + (k + kk) * 128;
            ulonglong2 b01 = *(const ulonglong2*)bp;
            ulonglong2 b23 = *(const ulonglong2*)(bp + 4);
#pragma unroll
            for (int r = 0; r < 8; ++r) {
                float av = (kk == 0) ? a4[r].x : (kk == 1) ? a4[r].y
                         : (kk == 2) ? a4[r].z : a4[r].w;
                unsigned long long ap = pack2(av);
                ffma2(acc[r][0], ap, b01.x);
                ffma2(acc[r][1], ap, b01.y);
                ffma2(acc[r][2], ap, b23.x);
                ffma2(acc[r][3], ap, b23.y);
            }
        }
    }

    const float* bvp = bv + n_id * 8;
    float4 bva = __ldg((const float4*)bvp);
    float4 bvb = __ldg((const float4*)bvp + 1);
#pragma unroll
    for (int r = 0; r < 8; ++r) {
        float srow = ssum_s[m_id * 8 + r];
        float2 p0 = unpack2(acc[r][0]);
        float2 p1 = unpack2(acc[r][1]);
        float2 p2 = unpack2(acc[r][2]);
        float2 p3 = unpack2(acc[r][3]);
        float4 o0 = make_float4(fmaf(srow, bva.x, p0.x), fmaf(srow, bva.y, p0.y),
                                fmaf(srow, bva.z, p1.x), fmaf(srow, bva.w, p1.y));
        float4 o1 = make_float4(fmaf(srow, bvb.x, p2.x), fmaf(srow, bvb.y, p2.y),
                                fmaf(srow, bvb.z, p3.x), fmaf(srow, bvb.w, p3.y));
        float* op = out + (size_t)(row0 + m_id * 8 + r) * D_ + n_id * 8;
        *(float4*)op       = o0;
        *(float4*)(op + 4) = o1;
    }
}

extern "C" void kernel_launch(void* const* d_in, const int* in_sizes, int n_in,
                              void* d_out, int out_size) {
    const float* nodes = (const float*)d_in[0];
    const float* nbrs  = (const float*)d_in[1];
    const float* mask  = (const float*)d_in[2];
    const float* Wq    = (const float*)d_in[3];
    const float* bq    = (const float*)d_in[4];
    const float* Wk    = (const float*)d_in[5];
    const float* bk    = (const float*)d_in[6];
    const float* Wv    = (const float*)d_in[7];
    const float* bv    = (const float*)d_in[8];
    const float* waq   = (const float*)d_in[9];
    const float* wak   = (const float*)d_in[10];
    const float* ba    = (const float*)d_in[11];
    float* out = (float*)d_out;

    cudaFuncSetAttribute(gat_gemm, cudaFuncAttributeMaxDynamicSharedMemorySize,
                         B_SM_FLOATS * 4);

    gat_prologue<<<32, 128>>>(Wq, bq, Wk, bk, waq, wak, ba);
    gat_attn<<<ROWS / A_WARPS, A_WARPS * 32>>>(nodes, nbrs, mask);
    gat_gemm<<<ROWS / TILE_M, B_THREADS, B_SM_FLOATS * 4>>>(Wv, bv, out);
}